// round 13
// baseline (speedup 1.0000x reference)
#include <cuda_runtime.h>
#include <cuda_bf16.h>
#include <math.h>

// Problem constants
#define N_NODES 100000
#define N_EDGES 1600000
#define DFEAT   128
#define NCLS    40

// ---------------------------------------------------------------------------
// Device scratch (no allocations allowed)
// ---------------------------------------------------------------------------
__device__ __align__(16) float g_aggr[N_NODES * DFEAT];
__device__ __align__(16) float g_h   [N_NODES * DFEAT];
__device__ __align__(16) float g_h2  [N_NODES * DFEAT];
// bf16 shadow copies used ONLY by the aggregation gather (halves L2 traffic)
__device__ __align__(16) __nv_bfloat16 g_xb [N_NODES * DFEAT];
__device__ __align__(16) __nv_bfloat16 g_hb [N_NODES * DFEAT];
__device__ __align__(16) __nv_bfloat16 g_h2b[N_NODES * DFEAT];
__device__ int   g_deg   [N_NODES];
__device__ float g_deginv[N_NODES];
__device__ int   g_rowptr[N_NODES + 1];
__device__ int   g_cursor[N_NODES];
__device__ int   g_csr   [N_EDGES];
__device__ int   g_part  [128];
__device__ int   g_is64;   // 1 if edge_index buffer is int64, 0 if int32

#define SCAN_NBLK ((N_NODES + 1023) / 1024)   // 98

// ---------------------------------------------------------------------------
// Edge-index dtype detection + access
// ---------------------------------------------------------------------------
__global__ void detect_kernel(const int* __restrict__ ei32) {
    __shared__ int sOr;
    if (threadIdx.x == 0) sOr = 0;
    __syncthreads();
    int v = 0;
    for (int i = threadIdx.x; i < 8192; i += blockDim.x)
        v |= ei32[2 * i + 1];
    atomicOr(&sOr, v);
    __syncthreads();
    if (threadIdx.x == 0) g_is64 = (sOr == 0) ? 1 : 0;
}

__device__ __forceinline__ int edge_val(const int* ei, int is64, int idx) {
    if (is64) return (int)((const long long*)ei)[idx];
    return ei[idx];
}

// ---------------------------------------------------------------------------
// CSR construction: deg count -> exclusive scan -> scatter
// ---------------------------------------------------------------------------
__global__ void zero_deg_kernel() {
    int i = blockIdx.x * blockDim.x + threadIdx.x;
    if (i < N_NODES) g_deg[i] = 0;
}

__global__ void count_deg_kernel(const int* __restrict__ ei) {
    int e = blockIdx.x * blockDim.x + threadIdx.x;
    if (e < N_EDGES) {
        int is64 = g_is64;
        int dst = edge_val(ei, is64, N_EDGES + e);
        if ((unsigned)dst < (unsigned)N_NODES)
            atomicAdd(&g_deg[dst], 1);
    }
}

__global__ void scan_blocks_kernel() {
    __shared__ int wsum[8];
    int tid  = threadIdx.x;
    int base = blockIdx.x * 1024 + tid * 4;
    int v[4];
    int s = 0;
#pragma unroll
    for (int j = 0; j < 4; j++) {
        v[j] = (base + j < N_NODES) ? g_deg[base + j] : 0;
        s += v[j];
    }
    int lane = tid & 31, w = tid >> 5;
    int inc = s;
#pragma unroll
    for (int o = 1; o < 32; o <<= 1) {
        int y = __shfl_up_sync(0xffffffffu, inc, o);
        if (lane >= o) inc += y;
    }
    if (lane == 31) wsum[w] = inc;
    __syncthreads();
    if (w == 0) {
        int t = (lane < 8) ? wsum[lane] : 0;
#pragma unroll
        for (int o = 1; o < 8; o <<= 1) {
            int y = __shfl_up_sync(0xffffffffu, t, o);
            if (lane >= o) t += y;
        }
        if (lane < 8) wsum[lane] = t;
    }
    __syncthreads();
    int excl = inc - s + (w ? wsum[w - 1] : 0);
#pragma unroll
    for (int j = 0; j < 4; j++) {
        if (base + j < N_NODES) g_rowptr[base + j] = excl;
        excl += v[j];
    }
    if (tid == 0) g_part[blockIdx.x] = wsum[7];
}

__global__ void scan_part_kernel() {
    const int NP = SCAN_NBLK;
    __shared__ int ws[4];
    int tid  = threadIdx.x;
    int v    = (tid < NP) ? g_part[tid] : 0;
    int lane = tid & 31, w = tid >> 5;
    int inc = v;
#pragma unroll
    for (int o = 1; o < 32; o <<= 1) {
        int y = __shfl_up_sync(0xffffffffu, inc, o);
        if (lane >= o) inc += y;
    }
    if (lane == 31) ws[w] = inc;
    __syncthreads();
    if (tid == 0) {
        int c = 0;
#pragma unroll
        for (int i = 0; i < 4; i++) { int t = ws[i]; ws[i] = c; c += t; }
    }
    __syncthreads();
    int excl = inc - v + ws[w];
    if (tid < NP) g_part[tid] = excl;
    if (tid == NP - 1) g_rowptr[N_NODES] = excl + v;
}

__global__ void scan_add_kernel() {
    int i = blockIdx.x * blockDim.x + threadIdx.x;
    if (i < N_NODES) {
        int r = g_rowptr[i] + g_part[i >> 10];
        g_rowptr[i] = r;
        g_cursor[i] = r;
        g_deginv[i] = 1.0f / (float)max(g_deg[i], 1);
    }
}

__global__ void fill_csr_kernel(const int* __restrict__ ei) {
    int e = blockIdx.x * blockDim.x + threadIdx.x;
    if (e < N_EDGES) {
        int is64 = g_is64;
        int dst = edge_val(ei, is64, N_EDGES + e);
        if ((unsigned)dst < (unsigned)N_NODES) {
            int src = edge_val(ei, is64, e);
            if ((unsigned)src >= (unsigned)N_NODES) src = 0;
            int pos = atomicAdd(&g_cursor[dst], 1);
            g_csr[pos] = src;
        }
    }
}

// ---------------------------------------------------------------------------
// Feature source selection
// ---------------------------------------------------------------------------
__device__ __forceinline__ const float* pick_feat(const float* ext, int sel) {
    return sel == 0 ? ext : (sel == 1 ? g_h : g_h2);
}
__device__ __forceinline__ const __nv_bfloat16* pick_feat_b(int sel) {
    return sel == 0 ? g_xb : (sel == 1 ? g_hb : g_h2b);
}

// ---------------------------------------------------------------------------
// x -> bf16 shadow copy (once per call, feeds layer-0 aggregation gather)
// ---------------------------------------------------------------------------
__global__ void x_to_bf16_kernel(const float* __restrict__ x) {
    int i = blockIdx.x * blockDim.x + threadIdx.x;   // one float4 per thread
    const int total = N_NODES * DFEAT / 4;
    if (i < total) {
        float4 v = __ldg((const float4*)x + i);
        __nv_bfloat162 p0 = __floats2bfloat162_rn(v.x, v.y);
        __nv_bfloat162 p1 = __floats2bfloat162_rn(v.z, v.w);
        uint2 u;
        u.x = *(unsigned*)&p0;
        u.y = *(unsigned*)&p1;
        ((uint2*)g_xb)[i] = u;
    }
}

// ---------------------------------------------------------------------------
// Mean aggregation (bf16 gather, fp32 accumulate): one warp per node, lane
// owns 4 contiguous features (8B). 256B per edge instead of 512B.
// Output g_aggr stays fp32, same layout as before.
// ---------------------------------------------------------------------------
__global__ void aggregate_kernel(int sel) {
    int gw = (blockIdx.x * blockDim.x + threadIdx.x) >> 5;
    if (gw >= N_NODES) return;
    const __nv_bfloat16* feat = pick_feat_b(sel);
    int lane = threadIdx.x & 31;
    int s = g_rowptr[gw];
    int e = g_rowptr[gw + 1];
    float4 acc = make_float4(0.f, 0.f, 0.f, 0.f);
    const uint2* f2 = (const uint2*)feat;   // 4 bf16 per uint2; row = 32 uint2
    for (int b = s; b < e; b += 32) {
        int idx = 0;
        if (b + lane < e) idx = g_csr[b + lane];
        int cnt = min(32, e - b);
#pragma unroll 4
        for (int t = 0; t < cnt; t++) {
            int src = __shfl_sync(0xffffffffu, idx, t);
            uint2 v = __ldg(&f2[src * 32 + lane]);
            float2 f0 = __bfloat1622float2(*(__nv_bfloat162*)&v.x);
            float2 f1 = __bfloat1622float2(*(__nv_bfloat162*)&v.y);
            acc.x += f0.x; acc.y += f0.y; acc.z += f1.x; acc.w += f1.y;
        }
    }
    float di = g_deginv[gw];
    acc.x *= di; acc.y *= di; acc.z *= di; acc.w *= di;
    ((float4*)g_aggr)[gw * 32 + lane] = acc;
}

// ---------------------------------------------------------------------------
// tf32 helpers
// ---------------------------------------------------------------------------
__device__ __forceinline__ float f2tf32(float f) {
    unsigned u;
    asm volatile("cvt.rna.tf32.f32 %0, %1;" : "=r"(u) : "f"(f));
    return __uint_as_float(u);
}

__device__ __forceinline__ void mma_tf32(float c[4], const float a[4], const float b[2]) {
    asm volatile(
        "mma.sync.aligned.m16n8k8.row.col.f32.tf32.tf32.f32 "
        "{%0,%1,%2,%3}, {%4,%5,%6,%7}, {%8,%9}, {%0,%1,%2,%3};\n"
        : "+f"(c[0]), "+f"(c[1]), "+f"(c[2]), "+f"(c[3])
        : "r"(__float_as_uint(a[0])), "r"(__float_as_uint(a[1])),
          "r"(__float_as_uint(a[2])), "r"(__float_as_uint(a[3])),
          "r"(__float_as_uint(b[0])), "r"(__float_as_uint(b[1])));
}

// ---------------------------------------------------------------------------
// Tensor-core dual GEMM, D=128 -> 128 as one K=256 GEMM:
//   out = relu( [aggr | Ax] @ [Wl ; Wr] + b )
// Epilogue writes fp32 h (next layer GEMM input) AND bf16 copy (next gather).
// ---------------------------------------------------------------------------
__global__ __launch_bounds__(256) void dual_gemm128_tc_kernel(
    const float* __restrict__ Ax_ext, int ax_sel,
    const float* __restrict__ Wl, const float* __restrict__ Wr,
    const float* __restrict__ bias, int out_sel)
{
    __shared__ float sA[128 * 36];   // 128 rows x 32 k (tf32 bits), pad 4
    __shared__ float sB[32 * 132];   // 32 k x 128 n (tf32 bits), pad 4

    const float* Ax  = pick_feat(Ax_ext, ax_sel);
    float* out          = (out_sel == 1) ? g_h  : g_h2;
    __nv_bfloat16* outb = (out_sel == 1) ? g_hb : g_h2b;

    int tid  = threadIdx.x;
    int wid  = tid >> 5;
    int lane = tid & 31;
    int wm   = wid & 1;        // 0..1 : 64-row slice
    int wn   = wid >> 1;       // 0..3 : 32-col slice
    int tg   = lane & 3;       // thread-in-group
    int g    = lane >> 2;      // group id
    int rowBase = blockIdx.x * 128;

    float c[4][4][4];
#pragma unroll
    for (int mf = 0; mf < 4; mf++)
#pragma unroll
        for (int nf = 0; nf < 4; nf++)
#pragma unroll
            for (int i = 0; i < 4; i++) c[mf][nf][i] = 0.f;

    for (int kc = 0; kc < 256; kc += 32) {
        const float* srcA = (kc < 128) ? g_aggr : Ax;
        const float* srcW = (kc < 128) ? Wl : Wr;
        int kcl = kc & 127;

#pragma unroll
        for (int i = 0; i < 4; i++) {
            int q  = tid + i * 256;
            int r  = q >> 3, c4 = q & 7;
            int row = rowBase + r;
            float4 v = make_float4(0.f, 0.f, 0.f, 0.f);
            if (row < N_NODES)
                v = __ldg((const float4*)(srcA + row * 128 + kcl) + c4);
            float* d = &sA[r * 36 + c4 * 4];
            d[0] = f2tf32(v.x); d[1] = f2tf32(v.y);
            d[2] = f2tf32(v.z); d[3] = f2tf32(v.w);
        }
#pragma unroll
        for (int i = 0; i < 4; i++) {
            int q  = tid + i * 256;
            int r  = q >> 5, c4 = q & 31;
            float4 v = __ldg((const float4*)(srcW + (kcl + r) * 128) + c4);
            float* d = &sB[r * 132 + c4 * 4];
            d[0] = f2tf32(v.x); d[1] = f2tf32(v.y);
            d[2] = f2tf32(v.z); d[3] = f2tf32(v.w);
        }
        __syncthreads();

#pragma unroll
        for (int kk = 0; kk < 32; kk += 8) {
            float a[4][4];
#pragma unroll
            for (int mf = 0; mf < 4; mf++) {
                int r0 = (wm * 64 + mf * 16 + g) * 36 + kk + tg;
                a[mf][0] = sA[r0];
                a[mf][1] = sA[r0 + 8 * 36];
                a[mf][2] = sA[r0 + 4];
                a[mf][3] = sA[r0 + 8 * 36 + 4];
            }
            float b[4][2];
#pragma unroll
            for (int nf = 0; nf < 4; nf++) {
                int col = wn * 32 + nf * 8 + g;
                b[nf][0] = sB[(kk + tg) * 132 + col];
                b[nf][1] = sB[(kk + tg + 4) * 132 + col];
            }
#pragma unroll
            for (int mf = 0; mf < 4; mf++)
#pragma unroll
                for (int nf = 0; nf < 4; nf++)
                    mma_tf32(c[mf][nf], a[mf], b[nf]);
        }
        __syncthreads();
    }

    // Epilogue: bias + relu, fp32 + bf16 dual store.
#pragma unroll
    for (int mf = 0; mf < 4; mf++) {
        int row0 = rowBase + wm * 64 + mf * 16 + g;
#pragma unroll
        for (int nf = 0; nf < 4; nf++) {
            int col = wn * 32 + nf * 8 + 2 * tg;
            float2 bv = __ldg((const float2*)(bias + col));
            if (row0 < N_NODES) {
                float2 o;
                o.x = fmaxf(c[mf][nf][0] + bv.x, 0.f);
                o.y = fmaxf(c[mf][nf][1] + bv.y, 0.f);
                *(float2*)(out + row0 * 128 + col) = o;
                *(__nv_bfloat162*)(outb + row0 * 128 + col) =
                    __floats2bfloat162_rn(o.x, o.y);
            }
            if (row0 + 8 < N_NODES) {
                float2 o;
                o.x = fmaxf(c[mf][nf][2] + bv.x, 0.f);
                o.y = fmaxf(c[mf][nf][3] + bv.y, 0.f);
                *(float2*)(out + (row0 + 8) * 128 + col) = o;
                *(__nv_bfloat162*)(outb + (row0 + 8) * 128 + col) =
                    __floats2bfloat162_rn(o.x, o.y);
            }
        }
    }
}

// ---------------------------------------------------------------------------
// Dual GEMM, D=128 -> 40 + fused log_softmax (final layer, exact fp32).
// ---------------------------------------------------------------------------
__global__ __launch_bounds__(256) void dual_gemm40_lsm_kernel(
    const float* __restrict__ Wl, const float* __restrict__ Wr,
    const float* __restrict__ bias, float* __restrict__ out)
{
    __shared__ float sWl[40 * 36];
    __shared__ float sWr[40 * 36];
    __shared__ float sAa[64 * 36];
    __shared__ float sAx[64 * 36];
    __shared__ float sb[40];

    const float* Ax = g_h2;

    int tid = threadIdx.x;
    int ct  = tid & 7;
    int rt  = tid >> 3;
    int rowBase = blockIdx.x * 64;
    if (tid < 40) sb[tid] = __ldg(bias + tid);

    float acc[2][5];
#pragma unroll
    for (int m = 0; m < 2; m++)
#pragma unroll
        for (int n = 0; n < 5; n++) acc[m][n] = 0.f;

    for (int kc = 0; kc < 128; kc += 32) {
        for (int q = tid; q < 1280; q += 256) {
            int k = q / 40, j = q - k * 40;
            sWl[j * 36 + k] = __ldg(Wl + kc * 40 + q);
            sWr[j * 36 + k] = __ldg(Wr + kc * 40 + q);
        }
#pragma unroll
        for (int q = tid; q < 512; q += 256) {
            int r = q >> 3, c4 = q & 7;
            int row = rowBase + r;
            float4 va = make_float4(0.f, 0.f, 0.f, 0.f), vx = va;
            if (row < N_NODES) {
                va = __ldg((const float4*)(g_aggr + row * 128 + kc) + c4);
                vx = __ldg((const float4*)(Ax     + row * 128 + kc) + c4);
            }
            *(float4*)&sAa[r * 36 + c4 * 4] = va;
            *(float4*)&sAx[r * 36 + c4 * 4] = vx;
        }
        __syncthreads();
#pragma unroll
        for (int kk = 0; kk < 32; kk += 4) {
            float wl[5][4], wr[5][4];
#pragma unroll
            for (int n = 0; n < 5; n++) {
                float4 t0 = *(const float4*)&sWl[(ct * 5 + n) * 36 + kk];
                wl[n][0] = t0.x; wl[n][1] = t0.y; wl[n][2] = t0.z; wl[n][3] = t0.w;
                float4 t1 = *(const float4*)&sWr[(ct * 5 + n) * 36 + kk];
                wr[n][0] = t1.x; wr[n][1] = t1.y; wr[n][2] = t1.z; wr[n][3] = t1.w;
            }
#pragma unroll
            for (int m = 0; m < 2; m++) {
                float4 a0 = *(const float4*)&sAa[(rt * 2 + m) * 36 + kk];
                float4 a1 = *(const float4*)&sAx[(rt * 2 + m) * 36 + kk];
                float al[4] = {a0.x, a0.y, a0.z, a0.w};
                float ax[4] = {a1.x, a1.y, a1.z, a1.w};
#pragma unroll
                for (int u = 0; u < 4; u++)
#pragma unroll
                    for (int n = 0; n < 5; n++)
                        acc[m][n] += al[u] * wl[n][u] + ax[u] * wr[n][u];
            }
        }
        __syncthreads();
    }

#pragma unroll
    for (int m = 0; m < 2; m++) {
        int row = rowBase + rt * 2 + m;
        float v[5];
#pragma unroll
        for (int n = 0; n < 5; n++) v[n] = acc[m][n] + sb[ct * 5 + n];
        float mx = v[0];
#pragma unroll
        for (int n = 1; n < 5; n++) mx = fmaxf(mx, v[n]);
#pragma unroll
        for (int o = 1; o < 8; o <<= 1)
            mx = fmaxf(mx, __shfl_xor_sync(0xffffffffu, mx, o, 8));
        float s = 0.f;
#pragma unroll
        for (int n = 0; n < 5; n++) s += expf(v[n] - mx);
#pragma unroll
        for (int o = 1; o < 8; o <<= 1)
            s += __shfl_xor_sync(0xffffffffu, s, o, 8);
        float lse = logf(s) + mx;
        if (row < N_NODES) {
#pragma unroll
            for (int n = 0; n < 5; n++) out[row * 40 + ct * 5 + n] = v[n] - lse;
        }
    }
}

// ---------------------------------------------------------------------------
// Launch
// ---------------------------------------------------------------------------
extern "C" void kernel_launch(void* const* d_in, const int* in_sizes, int n_in,
                              void* d_out, int out_size) {
    const float* x   = (const float*)d_in[0];
    const int*   ei  = (const int*)d_in[1];
    const float* Wl0 = (const float*)d_in[2];
    const float* Wr0 = (const float*)d_in[3];
    const float* b0  = (const float*)d_in[4];
    const float* Wl1 = (const float*)d_in[5];
    const float* Wr1 = (const float*)d_in[6];
    const float* b1  = (const float*)d_in[7];
    const float* Wl2 = (const float*)d_in[8];
    const float* Wr2 = (const float*)d_in[9];
    const float* b2  = (const float*)d_in[10];
    float* out = (float*)d_out;

    const int GN  = (N_NODES + 255) / 256;
    const int GE  = (N_EDGES + 255) / 256;
    const int GW  = (N_NODES * 32 + 255) / 256;       // warp per node
    const int GT  = (N_NODES + 127) / 128;            // TC GEMM blocks
    const int GB  = (N_NODES + 63) / 64;              // final-layer blocks
    const int GC  = (N_NODES * DFEAT / 4 + 255) / 256; // x->bf16 blocks

    // CSR build (deterministic, rebuilt every call); x->bf16 in parallel order
    detect_kernel     <<<1, 256>>>(ei);
    zero_deg_kernel   <<<GN, 256>>>();
    x_to_bf16_kernel  <<<GC, 256>>>(x);
    count_deg_kernel  <<<GE, 256>>>(ei);
    scan_blocks_kernel<<<SCAN_NBLK, 256>>>();
    scan_part_kernel  <<<1, 128>>>();
    scan_add_kernel   <<<GN, 256>>>();
    fill_csr_kernel   <<<GE, 256>>>(ei);

    // Layer 0: gather bf16(x), GEMM on fp32 aggr + fp32 x
    aggregate_kernel      <<<GW, 256>>>(0);
    dual_gemm128_tc_kernel<<<GT, 256>>>(x, 0, Wl0, Wr0, b0, /*out=g_h*/1);

    // Layer 1
    aggregate_kernel      <<<GW, 256>>>(1);
    dual_gemm128_tc_kernel<<<GT, 256>>>(nullptr, 1, Wl1, Wr1, b1, /*out=g_h2*/2);

    // Layer 2: fused dual GEMM + log_softmax (exact fp32)
    aggregate_kernel      <<<GW, 256>>>(2);
    dual_gemm40_lsm_kernel<<<GB, 256>>>(Wl2, Wr2, b2, out);
}

// round 14
// speedup vs baseline: 1.1179x; 1.1179x over previous
#include <cuda_runtime.h>
#include <cuda_bf16.h>
#include <math.h>

// Problem constants
#define N_NODES 100000
#define N_EDGES 1600000
#define DFEAT   128
#define NCLS    40

// ---------------------------------------------------------------------------
// Device scratch (no allocations allowed)
// ---------------------------------------------------------------------------
__device__ __align__(16) float g_aggr[N_NODES * DFEAT];
__device__ __align__(16) float g_h   [N_NODES * DFEAT];
__device__ __align__(16) float g_h2  [N_NODES * DFEAT];
__device__ int   g_deg   [N_NODES];
__device__ float g_deginv[N_NODES];
__device__ int   g_rowptr[N_NODES + 1];
__device__ int   g_cursor[N_NODES];
__device__ int   g_csr   [N_EDGES];
__device__ int   g_part  [128];
__device__ int   g_is64;   // 1 if edge_index buffer is int64, 0 if int32

#define SCAN_NBLK ((N_NODES + 1023) / 1024)   // 98

// ---------------------------------------------------------------------------
// Edge-index dtype detection + access
// ---------------------------------------------------------------------------
__global__ void detect_kernel(const int* __restrict__ ei32) {
    __shared__ int sOr;
    if (threadIdx.x == 0) sOr = 0;
    __syncthreads();
    int v = 0;
    for (int i = threadIdx.x; i < 8192; i += blockDim.x)
        v |= ei32[2 * i + 1];
    atomicOr(&sOr, v);
    __syncthreads();
    if (threadIdx.x == 0) g_is64 = (sOr == 0) ? 1 : 0;
}

__device__ __forceinline__ int edge_val(const int* ei, int is64, int idx) {
    if (is64) return (int)((const long long*)ei)[idx];
    return ei[idx];
}

// ---------------------------------------------------------------------------
// CSR construction: deg count -> exclusive scan -> scatter
// ---------------------------------------------------------------------------
__global__ void zero_deg_kernel() {
    int i = blockIdx.x * blockDim.x + threadIdx.x;
    if (i < N_NODES) g_deg[i] = 0;
}

__global__ void count_deg_kernel(const int* __restrict__ ei) {
    int e = blockIdx.x * blockDim.x + threadIdx.x;
    if (e < N_EDGES) {
        int is64 = g_is64;
        int dst = edge_val(ei, is64, N_EDGES + e);
        if ((unsigned)dst < (unsigned)N_NODES)
            atomicAdd(&g_deg[dst], 1);
    }
}

__global__ void scan_blocks_kernel() {
    __shared__ int wsum[8];
    int tid  = threadIdx.x;
    int base = blockIdx.x * 1024 + tid * 4;
    int v[4];
    int s = 0;
#pragma unroll
    for (int j = 0; j < 4; j++) {
        v[j] = (base + j < N_NODES) ? g_deg[base + j] : 0;
        s += v[j];
    }
    int lane = tid & 31, w = tid >> 5;
    int inc = s;
#pragma unroll
    for (int o = 1; o < 32; o <<= 1) {
        int y = __shfl_up_sync(0xffffffffu, inc, o);
        if (lane >= o) inc += y;
    }
    if (lane == 31) wsum[w] = inc;
    __syncthreads();
    if (w == 0) {
        int t = (lane < 8) ? wsum[lane] : 0;
#pragma unroll
        for (int o = 1; o < 8; o <<= 1) {
            int y = __shfl_up_sync(0xffffffffu, t, o);
            if (lane >= o) t += y;
        }
        if (lane < 8) wsum[lane] = t;
    }
    __syncthreads();
    int excl = inc - s + (w ? wsum[w - 1] : 0);
#pragma unroll
    for (int j = 0; j < 4; j++) {
        if (base + j < N_NODES) g_rowptr[base + j] = excl;
        excl += v[j];
    }
    if (tid == 0) g_part[blockIdx.x] = wsum[7];
}

__global__ void scan_part_kernel() {
    const int NP = SCAN_NBLK;
    __shared__ int ws[4];
    int tid  = threadIdx.x;
    int v    = (tid < NP) ? g_part[tid] : 0;
    int lane = tid & 31, w = tid >> 5;
    int inc = v;
#pragma unroll
    for (int o = 1; o < 32; o <<= 1) {
        int y = __shfl_up_sync(0xffffffffu, inc, o);
        if (lane >= o) inc += y;
    }
    if (lane == 31) ws[w] = inc;
    __syncthreads();
    if (tid == 0) {
        int c = 0;
#pragma unroll
        for (int i = 0; i < 4; i++) { int t = ws[i]; ws[i] = c; c += t; }
    }
    __syncthreads();
    int excl = inc - v + ws[w];
    if (tid < NP) g_part[tid] = excl;
    if (tid == NP - 1) g_rowptr[N_NODES] = excl + v;
}

__global__ void scan_add_kernel() {
    int i = blockIdx.x * blockDim.x + threadIdx.x;
    if (i < N_NODES) {
        int r = g_rowptr[i] + g_part[i >> 10];
        g_rowptr[i] = r;
        g_cursor[i] = r;
        g_deginv[i] = 1.0f / (float)max(g_deg[i], 1);
    }
}

__global__ void fill_csr_kernel(const int* __restrict__ ei) {
    int e = blockIdx.x * blockDim.x + threadIdx.x;
    if (e < N_EDGES) {
        int is64 = g_is64;
        int dst = edge_val(ei, is64, N_EDGES + e);
        if ((unsigned)dst < (unsigned)N_NODES) {
            int src = edge_val(ei, is64, e);
            if ((unsigned)src >= (unsigned)N_NODES) src = 0;
            int pos = atomicAdd(&g_cursor[dst], 1);
            g_csr[pos] = src;
        }
    }
}

// ---------------------------------------------------------------------------
// Feature source selection
// ---------------------------------------------------------------------------
__device__ __forceinline__ const float* pick_feat(const float* ext, int sel) {
    return sel == 0 ? ext : (sel == 1 ? g_h : g_h2);
}

// ---------------------------------------------------------------------------
// Mean aggregation: one warp per node, lane owns 4 contiguous floats.
// ---------------------------------------------------------------------------
__global__ void aggregate_kernel(const float* __restrict__ feat_ext, int sel) {
    int gw = (blockIdx.x * blockDim.x + threadIdx.x) >> 5;
    if (gw >= N_NODES) return;
    const float* feat = pick_feat(feat_ext, sel);
    int lane = threadIdx.x & 31;
    int s = g_rowptr[gw];
    int e = g_rowptr[gw + 1];
    float4 acc = make_float4(0.f, 0.f, 0.f, 0.f);
    const float4* f4 = (const float4*)feat;
    for (int b = s; b < e; b += 32) {
        int idx = 0;
        if (b + lane < e) idx = g_csr[b + lane];
        int cnt = min(32, e - b);
#pragma unroll 4
        for (int t = 0; t < cnt; t++) {
            int src = __shfl_sync(0xffffffffu, idx, t);
            float4 v = __ldg(&f4[src * 32 + lane]);
            acc.x += v.x; acc.y += v.y; acc.z += v.z; acc.w += v.w;
        }
    }
    float di = g_deginv[gw];
    acc.x *= di; acc.y *= di; acc.z *= di; acc.w *= di;
    ((float4*)g_aggr)[gw * 32 + lane] = acc;
}

// ---------------------------------------------------------------------------
// tf32 helpers
// ---------------------------------------------------------------------------
__device__ __forceinline__ float f2tf32(float f) {
    unsigned u;
    asm volatile("cvt.rna.tf32.f32 %0, %1;" : "=r"(u) : "f"(f));
    return __uint_as_float(u);
}

__device__ __forceinline__ void mma_tf32(float c[4], const float a[4], const float b[2]) {
    asm volatile(
        "mma.sync.aligned.m16n8k8.row.col.f32.tf32.tf32.f32 "
        "{%0,%1,%2,%3}, {%4,%5,%6,%7}, {%8,%9}, {%0,%1,%2,%3};\n"
        : "+f"(c[0]), "+f"(c[1]), "+f"(c[2]), "+f"(c[3])
        : "r"(__float_as_uint(a[0])), "r"(__float_as_uint(a[1])),
          "r"(__float_as_uint(a[2])), "r"(__float_as_uint(a[3])),
          "r"(__float_as_uint(b[0])), "r"(__float_as_uint(b[1])));
}

// ---------------------------------------------------------------------------
// Tensor-core dual GEMM, D=128 -> 128 as one K=256 GEMM:
//   out = relu( [aggr | Ax] @ [Wl ; Wr] + b )
// BM=128, BN=128, 256 threads = 8 warps (2M x 4N), warp = 64x32 via 4x4
// m16n8k8 tf32 fragments. smem strides 36/132 -> conflict-free.
// ---------------------------------------------------------------------------
__global__ __launch_bounds__(256) void dual_gemm128_tc_kernel(
    const float* __restrict__ Ax_ext, int ax_sel,
    const float* __restrict__ Wl, const float* __restrict__ Wr,
    const float* __restrict__ bias, int out_sel)
{
    __shared__ float sA[128 * 36];
    __shared__ float sB[32 * 132];

    const float* Ax  = pick_feat(Ax_ext, ax_sel);
    float* out = (out_sel == 1) ? g_h : g_h2;

    int tid  = threadIdx.x;
    int wid  = tid >> 5;
    int lane = tid & 31;
    int wm   = wid & 1;
    int wn   = wid >> 1;
    int tg   = lane & 3;
    int g    = lane >> 2;
    int rowBase = blockIdx.x * 128;

    float c[4][4][4];
#pragma unroll
    for (int mf = 0; mf < 4; mf++)
#pragma unroll
        for (int nf = 0; nf < 4; nf++)
#pragma unroll
            for (int i = 0; i < 4; i++) c[mf][nf][i] = 0.f;

    for (int kc = 0; kc < 256; kc += 32) {
        const float* srcA = (kc < 128) ? g_aggr : Ax;
        const float* srcW = (kc < 128) ? Wl : Wr;
        int kcl = kc & 127;

#pragma unroll
        for (int i = 0; i < 4; i++) {
            int q  = tid + i * 256;
            int r  = q >> 3, c4 = q & 7;
            int row = rowBase + r;
            float4 v = make_float4(0.f, 0.f, 0.f, 0.f);
            if (row < N_NODES)
                v = __ldg((const float4*)(srcA + row * 128 + kcl) + c4);
            float* d = &sA[r * 36 + c4 * 4];
            d[0] = f2tf32(v.x); d[1] = f2tf32(v.y);
            d[2] = f2tf32(v.z); d[3] = f2tf32(v.w);
        }
#pragma unroll
        for (int i = 0; i < 4; i++) {
            int q  = tid + i * 256;
            int r  = q >> 5, c4 = q & 31;
            float4 v = __ldg((const float4*)(srcW + (kcl + r) * 128) + c4);
            float* d = &sB[r * 132 + c4 * 4];
            d[0] = f2tf32(v.x); d[1] = f2tf32(v.y);
            d[2] = f2tf32(v.z); d[3] = f2tf32(v.w);
        }
        __syncthreads();

#pragma unroll
        for (int kk = 0; kk < 32; kk += 8) {
            float a[4][4];
#pragma unroll
            for (int mf = 0; mf < 4; mf++) {
                int r0 = (wm * 64 + mf * 16 + g) * 36 + kk + tg;
                a[mf][0] = sA[r0];
                a[mf][1] = sA[r0 + 8 * 36];
                a[mf][2] = sA[r0 + 4];
                a[mf][3] = sA[r0 + 8 * 36 + 4];
            }
            float b[4][2];
#pragma unroll
            for (int nf = 0; nf < 4; nf++) {
                int col = wn * 32 + nf * 8 + g;
                b[nf][0] = sB[(kk + tg) * 132 + col];
                b[nf][1] = sB[(kk + tg + 4) * 132 + col];
            }
#pragma unroll
            for (int mf = 0; mf < 4; mf++)
#pragma unroll
                for (int nf = 0; nf < 4; nf++)
                    mma_tf32(c[mf][nf], a[mf], b[nf]);
        }
        __syncthreads();
    }

#pragma unroll
    for (int mf = 0; mf < 4; mf++) {
        int row0 = rowBase + wm * 64 + mf * 16 + g;
#pragma unroll
        for (int nf = 0; nf < 4; nf++) {
            int col = wn * 32 + nf * 8 + 2 * tg;
            float2 bv = __ldg((const float2*)(bias + col));
            if (row0 < N_NODES) {
                float2 o;
                o.x = fmaxf(c[mf][nf][0] + bv.x, 0.f);
                o.y = fmaxf(c[mf][nf][1] + bv.y, 0.f);
                *(float2*)(out + row0 * 128 + col) = o;
            }
            if (row0 + 8 < N_NODES) {
                float2 o;
                o.x = fmaxf(c[mf][nf][2] + bv.x, 0.f);
                o.y = fmaxf(c[mf][nf][3] + bv.y, 0.f);
                *(float2*)(out + (row0 + 8) * 128 + col) = o;
            }
        }
    }
}

// ---------------------------------------------------------------------------
// Tensor-core dual GEMM, D=128 -> 40 + fused log_softmax (final layer):
//   out = log_softmax( [aggr | h2] @ [Wl2 ; Wr2] + b )
// BM=128 rows/block, 8 warps, each warp 16 rows x 40 cols = 5 m16n8k8
// fragments. sB stride 44: b-load banks = g + 12*tg (all distinct).
// Fragment layout puts a 40-col row on 4 adjacent lanes -> width-4 shuffles.
// ---------------------------------------------------------------------------
__global__ __launch_bounds__(256) void dual_gemm40_tc_lsm_kernel(
    const float* __restrict__ Wl, const float* __restrict__ Wr,
    const float* __restrict__ bias, float* __restrict__ out)
{
    __shared__ float sA[128 * 36];
    __shared__ float sB[32 * 44];
    __shared__ float sb[40];

    int tid  = threadIdx.x;
    int wid  = tid >> 5;
    int lane = tid & 31;
    int tg   = lane & 3;
    int g    = lane >> 2;
    int rowBase = blockIdx.x * 128;
    if (tid < 40) sb[tid] = __ldg(bias + tid);

    float c[5][4];
#pragma unroll
    for (int nf = 0; nf < 5; nf++)
#pragma unroll
        for (int i = 0; i < 4; i++) c[nf][i] = 0.f;

    for (int kc = 0; kc < 256; kc += 32) {
        const float* srcA = (kc < 128) ? g_aggr : g_h2;
        const float* srcW = (kc < 128) ? Wl : Wr;
        int kcl = kc & 127;

#pragma unroll
        for (int i = 0; i < 4; i++) {
            int q  = tid + i * 256;
            int r  = q >> 3, c4 = q & 7;
            int row = rowBase + r;
            float4 v = make_float4(0.f, 0.f, 0.f, 0.f);
            if (row < N_NODES)
                v = __ldg((const float4*)(srcA + row * 128 + kcl) + c4);
            float* d = &sA[r * 36 + c4 * 4];
            d[0] = f2tf32(v.x); d[1] = f2tf32(v.y);
            d[2] = f2tf32(v.z); d[3] = f2tf32(v.w);
        }
        // W chunk: [32 k x 40 n] contiguous floats -> sB[k*44 + j]
        for (int q = tid; q < 1280; q += 256) {
            int k = q / 40, j = q - k * 40;
            sB[k * 44 + j] = f2tf32(__ldg(srcW + kcl * 40 + q));
        }
        __syncthreads();

#pragma unroll
        for (int kk = 0; kk < 32; kk += 8) {
            float a[4];
            {
                int r0 = (wid * 16 + g) * 36 + kk + tg;
                a[0] = sA[r0];
                a[1] = sA[r0 + 8 * 36];
                a[2] = sA[r0 + 4];
                a[3] = sA[r0 + 8 * 36 + 4];
            }
            float b[5][2];
#pragma unroll
            for (int nf = 0; nf < 5; nf++) {
                int col = nf * 8 + g;
                b[nf][0] = sB[(kk + tg) * 44 + col];
                b[nf][1] = sB[(kk + tg + 4) * 44 + col];
            }
#pragma unroll
            for (int nf = 0; nf < 5; nf++)
                mma_tf32(c[nf], a, b[nf]);
        }
        __syncthreads();
    }

    // Fused bias + log_softmax. Row r0 = rowBase + wid*16 + g lives in
    // c[nf][0..1] on lanes tg=0..3 of this g-group; row r0+8 in c[nf][2..3].
#pragma unroll
    for (int half = 0; half < 2; half++) {
        int row = rowBase + wid * 16 + g + half * 8;
        float v[5][2];
#pragma unroll
        for (int nf = 0; nf < 5; nf++) {
            int col = nf * 8 + 2 * tg;
            v[nf][0] = c[nf][2 * half]     + sb[col];
            v[nf][1] = c[nf][2 * half + 1] + sb[col + 1];
        }
        float mx = -1e30f;
#pragma unroll
        for (int nf = 0; nf < 5; nf++)
            mx = fmaxf(mx, fmaxf(v[nf][0], v[nf][1]));
        mx = fmaxf(mx, __shfl_xor_sync(0xffffffffu, mx, 1));
        mx = fmaxf(mx, __shfl_xor_sync(0xffffffffu, mx, 2));
        float s = 0.f;
#pragma unroll
        for (int nf = 0; nf < 5; nf++)
            s += expf(v[nf][0] - mx) + expf(v[nf][1] - mx);
        s += __shfl_xor_sync(0xffffffffu, s, 1);
        s += __shfl_xor_sync(0xffffffffu, s, 2);
        float lse = logf(s) + mx;
        if (row < N_NODES) {
#pragma unroll
            for (int nf = 0; nf < 5; nf++) {
                float2 o = make_float2(v[nf][0] - lse, v[nf][1] - lse);
                *(float2*)(out + row * 40 + nf * 8 + 2 * tg) = o;
            }
        }
    }
}

// ---------------------------------------------------------------------------
// Launch
// ---------------------------------------------------------------------------
extern "C" void kernel_launch(void* const* d_in, const int* in_sizes, int n_in,
                              void* d_out, int out_size) {
    const float* x   = (const float*)d_in[0];
    const int*   ei  = (const int*)d_in[1];
    const float* Wl0 = (const float*)d_in[2];
    const float* Wr0 = (const float*)d_in[3];
    const float* b0  = (const float*)d_in[4];
    const float* Wl1 = (const float*)d_in[5];
    const float* Wr1 = (const float*)d_in[6];
    const float* b1  = (const float*)d_in[7];
    const float* Wl2 = (const float*)d_in[8];
    const float* Wr2 = (const float*)d_in[9];
    const float* b2  = (const float*)d_in[10];
    float* out = (float*)d_out;

    const int GN  = (N_NODES + 255) / 256;
    const int GE  = (N_EDGES + 255) / 256;
    const int GW  = (N_NODES * 32 + 255) / 256;       // warp per node
    const int GT  = (N_NODES + 127) / 128;            // TC GEMM blocks

    // CSR build (deterministic, rebuilt every call)
    detect_kernel     <<<1, 256>>>(ei);
    zero_deg_kernel   <<<GN, 256>>>();
    count_deg_kernel  <<<GE, 256>>>(ei);
    scan_blocks_kernel<<<SCAN_NBLK, 256>>>();
    scan_part_kernel  <<<1, 128>>>();
    scan_add_kernel   <<<GN, 256>>>();
    fill_csr_kernel   <<<GE, 256>>>(ei);

    // Layer 0
    aggregate_kernel      <<<GW, 256>>>(x, 0);
    dual_gemm128_tc_kernel<<<GT, 256>>>(x, 0, Wl0, Wr0, b0, /*out=g_h*/1);

    // Layer 1
    aggregate_kernel      <<<GW, 256>>>(nullptr, 1);
    dual_gemm128_tc_kernel<<<GT, 256>>>(nullptr, 1, Wl1, Wr1, b1, /*out=g_h2*/2);

    // Layer 2: tensor-core dual GEMM + fused log_softmax
    aggregate_kernel      <<<GW, 256>>>(nullptr, 2);
    dual_gemm40_tc_lsm_kernel<<<GT, 256>>>(Wl2, Wr2, b2, out);
}

// round 15
// speedup vs baseline: 1.1617x; 1.0392x over previous
#include <cuda_runtime.h>
#include <cuda_bf16.h>
#include <math.h>

// Problem constants
#define N_NODES 100000
#define N_EDGES 1600000
#define DFEAT   128
#define NCLS    40

// ---------------------------------------------------------------------------
// Device scratch (no allocations allowed)
// ---------------------------------------------------------------------------
__device__ __align__(16) float g_aggr[N_NODES * DFEAT];
__device__ __align__(16) float g_h   [N_NODES * DFEAT];
__device__ __align__(16) float g_h2  [N_NODES * DFEAT];
__device__ int   g_deg   [N_NODES];
__device__ float g_deginv[N_NODES];
__device__ int   g_rowptr[N_NODES + 1];
__device__ int   g_cursor[N_NODES];
__device__ int   g_csr   [N_EDGES];
__device__ int   g_part  [128];
__device__ int   g_is64;   // 1 if edge_index buffer is int64, 0 if int32

#define SCAN_NBLK ((N_NODES + 1023) / 1024)   // 98

// ---------------------------------------------------------------------------
// Edge-index dtype detection + access
// ---------------------------------------------------------------------------
__global__ void detect_kernel(const int* __restrict__ ei32) {
    __shared__ int sOr;
    if (threadIdx.x == 0) sOr = 0;
    __syncthreads();
    int v = 0;
    for (int i = threadIdx.x; i < 8192; i += blockDim.x)
        v |= ei32[2 * i + 1];
    atomicOr(&sOr, v);
    __syncthreads();
    if (threadIdx.x == 0) g_is64 = (sOr == 0) ? 1 : 0;
}

__device__ __forceinline__ int edge_val(const int* ei, int is64, int idx) {
    if (is64) return (int)((const long long*)ei)[idx];
    return ei[idx];
}

// ---------------------------------------------------------------------------
// CSR construction: deg count -> exclusive scan -> scatter
// ---------------------------------------------------------------------------
__global__ void zero_deg_kernel() {
    int i = blockIdx.x * blockDim.x + threadIdx.x;
    if (i < N_NODES) g_deg[i] = 0;
}

__global__ void count_deg_kernel(const int* __restrict__ ei) {
    int e = blockIdx.x * blockDim.x + threadIdx.x;
    if (e < N_EDGES) {
        int is64 = g_is64;
        int dst = edge_val(ei, is64, N_EDGES + e);
        if ((unsigned)dst < (unsigned)N_NODES)
            atomicAdd(&g_deg[dst], 1);
    }
}

__global__ void scan_blocks_kernel() {
    __shared__ int wsum[8];
    int tid  = threadIdx.x;
    int base = blockIdx.x * 1024 + tid * 4;
    int v[4];
    int s = 0;
#pragma unroll
    for (int j = 0; j < 4; j++) {
        v[j] = (base + j < N_NODES) ? g_deg[base + j] : 0;
        s += v[j];
    }
    int lane = tid & 31, w = tid >> 5;
    int inc = s;
#pragma unroll
    for (int o = 1; o < 32; o <<= 1) {
        int y = __shfl_up_sync(0xffffffffu, inc, o);
        if (lane >= o) inc += y;
    }
    if (lane == 31) wsum[w] = inc;
    __syncthreads();
    if (w == 0) {
        int t = (lane < 8) ? wsum[lane] : 0;
#pragma unroll
        for (int o = 1; o < 8; o <<= 1) {
            int y = __shfl_up_sync(0xffffffffu, t, o);
            if (lane >= o) t += y;
        }
        if (lane < 8) wsum[lane] = t;
    }
    __syncthreads();
    int excl = inc - s + (w ? wsum[w - 1] : 0);
#pragma unroll
    for (int j = 0; j < 4; j++) {
        if (base + j < N_NODES) g_rowptr[base + j] = excl;
        excl += v[j];
    }
    if (tid == 0) g_part[blockIdx.x] = wsum[7];
}

__global__ void scan_part_kernel() {
    const int NP = SCAN_NBLK;
    __shared__ int ws[4];
    int tid  = threadIdx.x;
    int v    = (tid < NP) ? g_part[tid] : 0;
    int lane = tid & 31, w = tid >> 5;
    int inc = v;
#pragma unroll
    for (int o = 1; o < 32; o <<= 1) {
        int y = __shfl_up_sync(0xffffffffu, inc, o);
        if (lane >= o) inc += y;
    }
    if (lane == 31) ws[w] = inc;
    __syncthreads();
    if (tid == 0) {
        int c = 0;
#pragma unroll
        for (int i = 0; i < 4; i++) { int t = ws[i]; ws[i] = c; c += t; }
    }
    __syncthreads();
    int excl = inc - v + ws[w];
    if (tid < NP) g_part[tid] = excl;
    if (tid == NP - 1) g_rowptr[N_NODES] = excl + v;
}

__global__ void scan_add_kernel() {
    int i = blockIdx.x * blockDim.x + threadIdx.x;
    if (i < N_NODES) {
        int r = g_rowptr[i] + g_part[i >> 10];
        g_rowptr[i] = r;
        g_cursor[i] = r;
        g_deginv[i] = 1.0f / (float)max(g_deg[i], 1);
    }
}

__global__ void fill_csr_kernel(const int* __restrict__ ei) {
    int e = blockIdx.x * blockDim.x + threadIdx.x;
    if (e < N_EDGES) {
        int is64 = g_is64;
        int dst = edge_val(ei, is64, N_EDGES + e);
        if ((unsigned)dst < (unsigned)N_NODES) {
            int src = edge_val(ei, is64, e);
            if ((unsigned)src >= (unsigned)N_NODES) src = 0;
            int pos = atomicAdd(&g_cursor[dst], 1);
            g_csr[pos] = src;
        }
    }
}

// ---------------------------------------------------------------------------
// Feature source selection
// ---------------------------------------------------------------------------
__device__ __forceinline__ const float* pick_feat(const float* ext, int sel) {
    return sel == 0 ? ext : (sel == 1 ? g_h : g_h2);
}

// ---------------------------------------------------------------------------
// Mean aggregation: one warp per node, lane owns 4 contiguous floats.
// (unchanged from R14 to isolate the GEMM change)
// ---------------------------------------------------------------------------
__global__ void aggregate_kernel(const float* __restrict__ feat_ext, int sel) {
    int gw = (blockIdx.x * blockDim.x + threadIdx.x) >> 5;
    if (gw >= N_NODES) return;
    const float* feat = pick_feat(feat_ext, sel);
    int lane = threadIdx.x & 31;
    int s = g_rowptr[gw];
    int e = g_rowptr[gw + 1];
    float4 acc = make_float4(0.f, 0.f, 0.f, 0.f);
    const float4* f4 = (const float4*)feat;
    for (int b = s; b < e; b += 32) {
        int idx = 0;
        if (b + lane < e) idx = g_csr[b + lane];
        int cnt = min(32, e - b);
#pragma unroll 4
        for (int t = 0; t < cnt; t++) {
            int src = __shfl_sync(0xffffffffu, idx, t);
            float4 v = __ldg(&f4[src * 32 + lane]);
            acc.x += v.x; acc.y += v.y; acc.z += v.z; acc.w += v.w;
        }
    }
    float di = g_deginv[gw];
    acc.x *= di; acc.y *= di; acc.z *= di; acc.w *= di;
    ((float4*)g_aggr)[gw * 32 + lane] = acc;
}

// ---------------------------------------------------------------------------
// tf32 mma (raw fp32 bits fed as tf32: HW ignores low mantissa bits)
// ---------------------------------------------------------------------------
__device__ __forceinline__ void mma_tf32(float c[4], const float a[4], const float b[2]) {
    asm volatile(
        "mma.sync.aligned.m16n8k8.row.col.f32.tf32.tf32.f32 "
        "{%0,%1,%2,%3}, {%4,%5,%6,%7}, {%8,%9}, {%0,%1,%2,%3};\n"
        : "+f"(c[0]), "+f"(c[1]), "+f"(c[2]), "+f"(c[3])
        : "r"(__float_as_uint(a[0])), "r"(__float_as_uint(a[1])),
          "r"(__float_as_uint(a[2])), "r"(__float_as_uint(a[3])),
          "r"(__float_as_uint(b[0])), "r"(__float_as_uint(b[1])));
}

// ---------------------------------------------------------------------------
// Tensor-core dual GEMM, D=128 -> 128 as one K=256 GEMM:
//   out = relu( [aggr | Ax] @ [Wl ; Wr] + b )
// Pipelined: chunk k+1 is loaded into registers while chunk k's MMAs run.
// Fills are raw float4 copies (no cvt), vector STS.
// ---------------------------------------------------------------------------
__global__ __launch_bounds__(256) void dual_gemm128_tc_kernel(
    const float* __restrict__ Ax_ext, int ax_sel,
    const float* __restrict__ Wl, const float* __restrict__ Wr,
    const float* __restrict__ bias, int out_sel)
{
    __shared__ float sA[128 * 36];
    __shared__ float sB[32 * 132];

    const float* Ax  = pick_feat(Ax_ext, ax_sel);
    float* out = (out_sel == 1) ? g_h : g_h2;

    int tid  = threadIdx.x;
    int wid  = tid >> 5;
    int lane = tid & 31;
    int wm   = wid & 1;
    int wn   = wid >> 1;
    int tg   = lane & 3;
    int g    = lane >> 2;
    int rowBase = blockIdx.x * 128;

    // Per-thread fill coordinates (fixed across chunks)
    int ra[4], ca[4], rb[4], cb[4];
#pragma unroll
    for (int i = 0; i < 4; i++) {
        int q = tid + i * 256;
        ra[i] = q >> 3; ca[i] = q & 7;      // A: 128 rows x 8 float4
        rb[i] = q >> 5; cb[i] = q & 31;     // B: 32 k x 32 float4
    }

    float c[4][4][4];
#pragma unroll
    for (int mf = 0; mf < 4; mf++)
#pragma unroll
        for (int nf = 0; nf < 4; nf++)
#pragma unroll
            for (int i = 0; i < 4; i++) c[mf][nf][i] = 0.f;

    float4 pa[4], pb[4];

    // Prefetch chunk 0
    {
        const float* srcA = g_aggr;
        const float* srcW = Wl;
#pragma unroll
        for (int i = 0; i < 4; i++) {
            int row = rowBase + ra[i];
            pa[i] = make_float4(0.f, 0.f, 0.f, 0.f);
            if (row < N_NODES)
                pa[i] = __ldg((const float4*)(srcA + row * 128) + ca[i]);
            pb[i] = __ldg((const float4*)(srcW + rb[i] * 128) + cb[i]);
        }
    }

    for (int kc = 0; kc < 256; kc += 32) {
        // Store prefetched chunk to smem (vector STS, no cvt)
#pragma unroll
        for (int i = 0; i < 4; i++) {
            *(float4*)&sA[ra[i] * 36 + ca[i] * 4] = pa[i];
            *(float4*)&sB[rb[i] * 132 + cb[i] * 4] = pb[i];
        }
        __syncthreads();

        // Prefetch next chunk while MMAs run
        int kn = kc + 32;
        if (kn < 256) {
            const float* srcA = (kn < 128) ? g_aggr : Ax;
            const float* srcW = (kn < 128) ? Wl : Wr;
            int knl = kn & 127;
#pragma unroll
            for (int i = 0; i < 4; i++) {
                int row = rowBase + ra[i];
                pa[i] = make_float4(0.f, 0.f, 0.f, 0.f);
                if (row < N_NODES)
                    pa[i] = __ldg((const float4*)(srcA + row * 128 + knl) + ca[i]);
                pb[i] = __ldg((const float4*)(srcW + (knl + rb[i]) * 128) + cb[i]);
            }
        }

#pragma unroll
        for (int kk = 0; kk < 32; kk += 8) {
            float a[4][4];
#pragma unroll
            for (int mf = 0; mf < 4; mf++) {
                int r0 = (wm * 64 + mf * 16 + g) * 36 + kk + tg;
                a[mf][0] = sA[r0];
                a[mf][1] = sA[r0 + 8 * 36];
                a[mf][2] = sA[r0 + 4];
                a[mf][3] = sA[r0 + 8 * 36 + 4];
            }
            float b[4][2];
#pragma unroll
            for (int nf = 0; nf < 4; nf++) {
                int col = wn * 32 + nf * 8 + g;
                b[nf][0] = sB[(kk + tg) * 132 + col];
                b[nf][1] = sB[(kk + tg + 4) * 132 + col];
            }
#pragma unroll
            for (int mf = 0; mf < 4; mf++)
#pragma unroll
                for (int nf = 0; nf < 4; nf++)
                    mma_tf32(c[mf][nf], a[mf], b[nf]);
        }
        __syncthreads();
    }

#pragma unroll
    for (int mf = 0; mf < 4; mf++) {
        int row0 = rowBase + wm * 64 + mf * 16 + g;
#pragma unroll
        for (int nf = 0; nf < 4; nf++) {
            int col = wn * 32 + nf * 8 + 2 * tg;
            float2 bv = __ldg((const float2*)(bias + col));
            if (row0 < N_NODES) {
                float2 o;
                o.x = fmaxf(c[mf][nf][0] + bv.x, 0.f);
                o.y = fmaxf(c[mf][nf][1] + bv.y, 0.f);
                *(float2*)(out + row0 * 128 + col) = o;
            }
            if (row0 + 8 < N_NODES) {
                float2 o;
                o.x = fmaxf(c[mf][nf][2] + bv.x, 0.f);
                o.y = fmaxf(c[mf][nf][3] + bv.y, 0.f);
                *(float2*)(out + (row0 + 8) * 128 + col) = o;
            }
        }
    }
}

// ---------------------------------------------------------------------------
// Tensor-core dual GEMM, D=128 -> 40 + fused log_softmax (final layer).
// Same pipeline treatment: raw-bit fills, vector STS for A, reg prefetch.
// ---------------------------------------------------------------------------
__global__ __launch_bounds__(256) void dual_gemm40_tc_lsm_kernel(
    const float* __restrict__ Wl, const float* __restrict__ Wr,
    const float* __restrict__ bias, float* __restrict__ out)
{
    __shared__ float sA[128 * 36];
    __shared__ float sB[32 * 44];
    __shared__ float sb[40];

    int tid  = threadIdx.x;
    int wid  = tid >> 5;
    int lane = tid & 31;
    int tg   = lane & 3;
    int g    = lane >> 2;
    int rowBase = blockIdx.x * 128;
    if (tid < 40) sb[tid] = __ldg(bias + tid);

    int ra[4], ca[4];
#pragma unroll
    for (int i = 0; i < 4; i++) {
        int q = tid + i * 256;
        ra[i] = q >> 3; ca[i] = q & 7;
    }
    // B fill: 1280 floats, 5 per thread at fixed offsets
    int qk[5], qj[5];
#pragma unroll
    for (int i = 0; i < 5; i++) {
        int q = tid + i * 256;
        qk[i] = q / 40; qj[i] = q - qk[i] * 40;
    }

    float c[5][4];
#pragma unroll
    for (int nf = 0; nf < 5; nf++)
#pragma unroll
        for (int i = 0; i < 4; i++) c[nf][i] = 0.f;

    float4 pa[4];
    float  pbv[5];

    // Prefetch chunk 0
    {
#pragma unroll
        for (int i = 0; i < 4; i++) {
            int row = rowBase + ra[i];
            pa[i] = make_float4(0.f, 0.f, 0.f, 0.f);
            if (row < N_NODES)
                pa[i] = __ldg((const float4*)(g_aggr + row * 128) + ca[i]);
        }
#pragma unroll
        for (int i = 0; i < 5; i++)
            pbv[i] = __ldg(Wl + qk[i] * 40 + qj[i]);
    }

    for (int kc = 0; kc < 256; kc += 32) {
#pragma unroll
        for (int i = 0; i < 4; i++)
            *(float4*)&sA[ra[i] * 36 + ca[i] * 4] = pa[i];
#pragma unroll
        for (int i = 0; i < 5; i++)
            sB[qk[i] * 44 + qj[i]] = pbv[i];
        __syncthreads();

        int kn = kc + 32;
        if (kn < 256) {
            const float* srcA = (kn < 128) ? g_aggr : g_h2;
            const float* srcW = (kn < 128) ? Wl : Wr;
            int knl = kn & 127;
#pragma unroll
            for (int i = 0; i < 4; i++) {
                int row = rowBase + ra[i];
                pa[i] = make_float4(0.f, 0.f, 0.f, 0.f);
                if (row < N_NODES)
                    pa[i] = __ldg((const float4*)(srcA + row * 128 + knl) + ca[i]);
            }
#pragma unroll
            for (int i = 0; i < 5; i++)
                pbv[i] = __ldg(srcW + (knl + qk[i]) * 40 + qj[i]);
        }

#pragma unroll
        for (int kk = 0; kk < 32; kk += 8) {
            float a[4];
            {
                int r0 = (wid * 16 + g) * 36 + kk + tg;
                a[0] = sA[r0];
                a[1] = sA[r0 + 8 * 36];
                a[2] = sA[r0 + 4];
                a[3] = sA[r0 + 8 * 36 + 4];
            }
            float b[5][2];
#pragma unroll
            for (int nf = 0; nf < 5; nf++) {
                int col = nf * 8 + g;
                b[nf][0] = sB[(kk + tg) * 44 + col];
                b[nf][1] = sB[(kk + tg + 4) * 44 + col];
            }
#pragma unroll
            for (int nf = 0; nf < 5; nf++)
                mma_tf32(c[nf], a, b[nf]);
        }
        __syncthreads();
    }

    // Fused bias + log_softmax (width-4 shuffles within each g-group).
#pragma unroll
    for (int half = 0; half < 2; half++) {
        int row = rowBase + wid * 16 + g + half * 8;
        float v[5][2];
#pragma unroll
        for (int nf = 0; nf < 5; nf++) {
            int col = nf * 8 + 2 * tg;
            v[nf][0] = c[nf][2 * half]     + sb[col];
            v[nf][1] = c[nf][2 * half + 1] + sb[col + 1];
        }
        float mx = -1e30f;
#pragma unroll
        for (int nf = 0; nf < 5; nf++)
            mx = fmaxf(mx, fmaxf(v[nf][0], v[nf][1]));
        mx = fmaxf(mx, __shfl_xor_sync(0xffffffffu, mx, 1));
        mx = fmaxf(mx, __shfl_xor_sync(0xffffffffu, mx, 2));
        float s = 0.f;
#pragma unroll
        for (int nf = 0; nf < 5; nf++)
            s += expf(v[nf][0] - mx) + expf(v[nf][1] - mx);
        s += __shfl_xor_sync(0xffffffffu, s, 1);
        s += __shfl_xor_sync(0xffffffffu, s, 2);
        float lse = logf(s) + mx;
        if (row < N_NODES) {
#pragma unroll
            for (int nf = 0; nf < 5; nf++) {
                float2 o = make_float2(v[nf][0] - lse, v[nf][1] - lse);
                *(float2*)(out + row * 40 + nf * 8 + 2 * tg) = o;
            }
        }
    }
}

// ---------------------------------------------------------------------------
// Launch
// ---------------------------------------------------------------------------
extern "C" void kernel_launch(void* const* d_in, const int* in_sizes, int n_in,
                              void* d_out, int out_size) {
    const float* x   = (const float*)d_in[0];
    const int*   ei  = (const int*)d_in[1];
    const float* Wl0 = (const float*)d_in[2];
    const float* Wr0 = (const float*)d_in[3];
    const float* b0  = (const float*)d_in[4];
    const float* Wl1 = (const float*)d_in[5];
    const float* Wr1 = (const float*)d_in[6];
    const float* b1  = (const float*)d_in[7];
    const float* Wl2 = (const float*)d_in[8];
    const float* Wr2 = (const float*)d_in[9];
    const float* b2  = (const float*)d_in[10];
    float* out = (float*)d_out;

    const int GN  = (N_NODES + 255) / 256;
    const int GE  = (N_EDGES + 255) / 256;
    const int GW  = (N_NODES * 32 + 255) / 256;       // warp per node
    const int GT  = (N_NODES + 127) / 128;            // TC GEMM blocks

    // CSR build (deterministic, rebuilt every call)
    detect_kernel     <<<1, 256>>>(ei);
    zero_deg_kernel   <<<GN, 256>>>();
    count_deg_kernel  <<<GE, 256>>>(ei);
    scan_blocks_kernel<<<SCAN_NBLK, 256>>>();
    scan_part_kernel  <<<1, 128>>>();
    scan_add_kernel   <<<GN, 256>>>();
    fill_csr_kernel   <<<GE, 256>>>(ei);

    // Layer 0
    aggregate_kernel      <<<GW, 256>>>(x, 0);
    dual_gemm128_tc_kernel<<<GT, 256>>>(x, 0, Wl0, Wr0, b0, /*out=g_h*/1);

    // Layer 1
    aggregate_kernel      <<<GW, 256>>>(nullptr, 1);
    dual_gemm128_tc_kernel<<<GT, 256>>>(nullptr, 1, Wl1, Wr1, b1, /*out=g_h2*/2);

    // Layer 2: tensor-core dual GEMM + fused log_softmax
    aggregate_kernel      <<<GW, 256>>>(nullptr, 2);
    dual_gemm40_tc_lsm_kernel<<<GT, 256>>>(Wl2, Wr2, b2, out);
}